// round 6
// baseline (speedup 1.0000x reference)
#include <cuda_runtime.h>
#include <cuda_bf16.h>
#include <math.h>

#define Bb 2
#define Ls 2048
#define Ds 1024
#define Hh 16
#define HDd 64
#define FFs 4096
#define BLn (Bb*Ls)
#define EPSf 1e-5f

// ---------------- scratch (static device memory) ----------------
__device__ float g_stage[BLn*Ds];
__device__ float g_q[BLn*Ds];
__device__ float g_k[BLn*Ds];
__device__ float g_v[BLn*Ds];
__device__ float g_tgt2[BLn*Ds];
__device__ float g_mem[BLn*Ds];
__device__ float g_h2[BLn*2*Ds];
__device__ float g_glu[BLn*Ds];
__device__ float g_conv[BLn*Ds];
__device__ float g_mem2[BLn*Ds];
__device__ float g_sum[BLn*Ds];
__device__ unsigned short g_ah[16777216];  // split pair 1 (max 4096x4096)
__device__ unsigned short g_al[16777216];
__device__ unsigned short g_bh[4194304];   // B-operand splits
__device__ unsigned short g_bl[4194304];
__device__ unsigned short g_ch[16777216];  // split pair 2
__device__ unsigned short g_cl[16777216];

// ---------------- helpers ----------------
__device__ __forceinline__ float fexp(float x)
{
    float t = x * 1.442695041f;
    t = fmaxf(t, -126.f);
    float fn = t + 12582912.f;
    int n = __float_as_int(fn) - 0x4B400000;
    float f = t - (fn - 12582912.f);
    float p = 1.33335581e-3f;
    p = fmaf(p, f, 9.61812910e-3f);
    p = fmaf(p, f, 5.55041087e-2f);
    p = fmaf(p, f, 2.40226507e-1f);
    p = fmaf(p, f, 6.93147180e-1f);
    p = fmaf(p, f, 1.0f);
    return __int_as_float((n + 127) << 23) * p;
}

__device__ __forceinline__ float gelu_exact(float v)
{
    return 0.5f * v * (1.f + erff(v * 0.70710678118654752f));
}

__device__ __forceinline__ void split2(float v, unsigned short& h, unsigned short& l)
{
    __nv_bfloat16 hb = __float2bfloat16_rn(v);
    h = __bfloat16_as_ushort(hb);
    l = __bfloat16_as_ushort(__float2bfloat16_rn(v - __bfloat162float(hb)));
}

// ---------------- split fp32 -> bf16 hi/lo ----------------
__global__ __launch_bounds__(256) void split_kernel(
    const float* __restrict__ x, unsigned short* __restrict__ hi,
    unsigned short* __restrict__ lo, long n)
{
    long i = ((long)blockIdx.x * 256 + threadIdx.x) * 4;
    if (i >= n) return;
    float4 v = *(const float4*)(x + i);
    ushort4 hv, lv;
    split2(v.x, hv.x, lv.x);
    split2(v.y, hv.y, lv.y);
    split2(v.z, hv.z, lv.z);
    split2(v.w, hv.w, lv.w);
    *(ushort4*)(hi + i) = hv;
    *(ushort4*)(lo + i) = lv;
}

// ---------------- transpose + split: in [R,C] fp32 -> out [C,R] bf16 hi/lo ----------------
__global__ __launch_bounds__(256) void splitT_kernel(
    const float* __restrict__ in, unsigned short* __restrict__ hiT,
    unsigned short* __restrict__ loT, int R, int C, long sz)
{
    __shared__ float t[32][33];
    const float* inz = in + (long)blockIdx.z * sz;
    unsigned short* hz = hiT + (long)blockIdx.z * sz;
    unsigned short* lz = loT + (long)blockIdx.z * sz;
    int tx = threadIdx.x, ty = threadIdx.y;
    int x = blockIdx.x * 32 + tx;
    int y0 = blockIdx.y * 32;
#pragma unroll
    for (int j = 0; j < 32; j += 8)
        t[ty + j][tx] = inz[(long)(y0 + ty + j) * C + x];
    __syncthreads();
    int ox = blockIdx.y * 32 + tx;
    int oy0 = blockIdx.x * 32;
#pragma unroll
    for (int j = 0; j < 32; j += 8) {
        float val = t[tx][ty + j];
        unsigned short h, l;
        split2(val, h, l);
        hz[(long)(oy0 + ty + j) * R + ox] = h;
        lz[(long)(oy0 + ty + j) * R + ox] = l;
    }
}

// ---------------- mma helpers ----------------
__device__ __forceinline__ unsigned smem_u32(const void* p)
{
    return (unsigned)__cvta_generic_to_shared(p);
}
__device__ __forceinline__ void cp16(unsigned s, const void* g)
{
    asm volatile("cp.async.cg.shared.global [%0], [%1], 16;" :: "r"(s), "l"(g));
}
__device__ __forceinline__ void cp_commit()
{
    asm volatile("cp.async.commit_group;");
}
__device__ __forceinline__ void cp_wait1()
{
    asm volatile("cp.async.wait_group 1;");
}
__device__ __forceinline__ void cp_wait0()
{
    asm volatile("cp.async.wait_group 0;");
}
__device__ __forceinline__ void ldsm4(unsigned& r0, unsigned& r1, unsigned& r2, unsigned& r3, unsigned a)
{
    asm volatile("ldmatrix.sync.aligned.m8n8.x4.shared.b16 {%0,%1,%2,%3}, [%4];"
        : "=r"(r0), "=r"(r1), "=r"(r2), "=r"(r3) : "r"(a));
}
__device__ __forceinline__ void ldsm2t(unsigned& r0, unsigned& r1, unsigned a)
{
    asm volatile("ldmatrix.sync.aligned.m8n8.x2.trans.shared.b16 {%0,%1}, [%2];"
        : "=r"(r0), "=r"(r1) : "r"(a));
}
__device__ __forceinline__ void mma16816(float* d, const unsigned* a, const unsigned* b)
{
    asm volatile("mma.sync.aligned.m16n8k16.row.col.f32.bf16.bf16.f32 "
        "{%0,%1,%2,%3}, {%4,%5,%6,%7}, {%8,%9}, {%0,%1,%2,%3};"
        : "+f"(d[0]), "+f"(d[1]), "+f"(d[2]), "+f"(d[3])
        : "r"(a[0]), "r"(a[1]), "r"(a[2]), "r"(a[3]), "r"(b[0]), "r"(b[1]));
}

// ---------------- bf16-split tensor-core GEMM (R3 proven + fused epilogue) ----------------
#define LDA_P 40
#define LDB_P 136
#define OFF_AL (128*40)
#define OFF_BH (2*128*40)
#define OFF_BL (2*128*40 + 32*136)
#define STAGE_ELEMS (2*128*40 + 2*32*136)
#define BG_SMEM_BYTES (2*STAGE_ELEMS*2)

__global__ __launch_bounds__(256, 1) void bgemm_kernel(
    const unsigned short* __restrict__ Ah, const unsigned short* __restrict__ Al,
    const unsigned short* __restrict__ Bh, const unsigned short* __restrict__ Bl,
    const float* __restrict__ bias, const float* __restrict__ addp,
    float* __restrict__ C, unsigned short* __restrict__ oh,
    unsigned short* __restrict__ ol, int M, int N, int K,
    long sB, long sC, int bias_mode, int act)
{
    extern __shared__ unsigned short smem[];
    const int tid = threadIdx.x;
    const int lane = tid & 31;
    const int warp = tid >> 5;
    const int bm = blockIdx.y * 128;
    const int bn = blockIdx.x * 128;
    const unsigned short* Bhz = Bh + (long)blockIdx.z * sB;
    const unsigned short* Blz = Bl + (long)blockIdx.z * sB;
    float* Cz = C ? (C + (long)blockIdx.z * sC) : (float*)0;
    unsigned short* ohz = oh ? (oh + (long)blockIdx.z * sC) : (unsigned short*)0;
    unsigned short* olz = ol ? (ol + (long)blockIdx.z * sC) : (unsigned short*)0;
    const float* addz = addp ? (addp + (long)blockIdx.z * sC) : (const float*)0;
    const int m0 = (warp & 1) * 64;
    const int n0 = (warp >> 1) * 32;

    const int ar0 = tid >> 1;
    const int ac0 = (tid & 1) * 16;
    const int br0 = tid >> 4;
    const int bc0 = (tid & 15) * 8;

    float acc[4][4][4];
#pragma unroll
    for (int mi = 0; mi < 4; mi++)
#pragma unroll
        for (int ni = 0; ni < 4; ni++)
#pragma unroll
            for (int qq = 0; qq < 4; qq++) acc[mi][ni][qq] = 0.f;

    const int nIter = K >> 5;

#pragma unroll 1
    for (int it = 0; it < nIter + 1; ++it) {
        if (it < nIter) {
            unsigned short* st = smem + (it & 1) * STAGE_ELEMS;
            int k0 = it << 5;
            {
                long ga = (long)(bm + ar0) * K + k0 + ac0;
                cp16(smem_u32(st + ar0 * LDA_P + ac0), Ah + ga);
                cp16(smem_u32(st + ar0 * LDA_P + ac0 + 8), Ah + ga + 8);
                cp16(smem_u32(st + OFF_AL + ar0 * LDA_P + ac0), Al + ga);
                cp16(smem_u32(st + OFF_AL + ar0 * LDA_P + ac0 + 8), Al + ga + 8);
            }
            {
                long gb0 = (long)(k0 + br0) * N + bn + bc0;
                long gb1 = (long)(k0 + br0 + 16) * N + bn + bc0;
                cp16(smem_u32(st + OFF_BH + br0 * LDB_P + bc0), Bhz + gb0);
                cp16(smem_u32(st + OFF_BH + (br0 + 16) * LDB_P + bc0), Bhz + gb1);
                cp16(smem_u32(st + OFF_BL + br0 * LDB_P + bc0), Blz + gb0);
                cp16(smem_u32(st + OFF_BL + (br0 + 16) * LDB_P + bc0), Blz + gb1);
            }
            cp_commit();
        }
        if (it == 0) continue;
        if (it < nIter) cp_wait1(); else cp_wait0();
        __syncthreads();

        unsigned short* cur = smem + ((it - 1) & 1) * STAGE_ELEMS;
#pragma unroll
        for (int ks = 0; ks < 32; ks += 16) {
            unsigned afh[4][4], afl[4][4], bfh[4][2], bfl[4][2];
#pragma unroll
            for (int mi = 0; mi < 4; mi++) {
                int row = m0 + mi * 16 + (lane & 15);
                int col = ks + (lane >> 4) * 8;
                ldsm4(afh[mi][0], afh[mi][1], afh[mi][2], afh[mi][3],
                      smem_u32(cur + row * LDA_P + col));
                ldsm4(afl[mi][0], afl[mi][1], afl[mi][2], afl[mi][3],
                      smem_u32(cur + OFF_AL + row * LDA_P + col));
            }
#pragma unroll
            for (int ni = 0; ni < 4; ni++) {
                int row = ks + (lane & 15);
                int col = n0 + ni * 8;
                ldsm2t(bfh[ni][0], bfh[ni][1], smem_u32(cur + OFF_BH + row * LDB_P + col));
                ldsm2t(bfl[ni][0], bfl[ni][1], smem_u32(cur + OFF_BL + row * LDB_P + col));
            }
#pragma unroll
            for (int mi = 0; mi < 4; mi++) {
#pragma unroll
                for (int ni = 0; ni < 4; ni++) {
                    mma16816(acc[mi][ni], afh[mi], bfh[ni]);
                    mma16816(acc[mi][ni], afh[mi], bfl[ni]);
                    mma16816(acc[mi][ni], afl[mi], bfh[ni]);
                }
            }
        }
        __syncthreads();
    }

    const int r4 = lane >> 2;
    const int c2 = (lane & 3) * 2;
#pragma unroll
    for (int mi = 0; mi < 4; mi++) {
#pragma unroll
        for (int ni = 0; ni < 4; ni++) {
            int col = bn + n0 + ni * 8 + c2;
#pragma unroll
            for (int hf = 0; hf < 2; hf++) {
                int row = bm + m0 + mi * 16 + r4 + hf * 8;
                float v0 = acc[mi][ni][hf * 2 + 0];
                float v1 = acc[mi][ni][hf * 2 + 1];
                if (bias_mode == 1) { v0 += bias[col]; v1 += bias[col + 1]; }
                if (bias_mode == 2) { float bv = bias[row]; v0 += bv; v1 += bv; }
                if (addz) {
                    v0 += addz[(long)row * N + col];
                    v1 += addz[(long)row * N + col + 1];
                }
                if (act == 1) { v0 = gelu_exact(v0); v1 = gelu_exact(v1); }
                long idx = (long)row * N + col;
                if (Cz) {
                    float2 ov;
                    ov.x = v0; ov.y = v1;
                    *(float2*)(Cz + idx) = ov;
                }
                if (ohz) {
                    ushort2 hv, lv;
                    split2(v0, hv.x, lv.x);
                    split2(v1, hv.y, lv.y);
                    *(ushort2*)(ohz + idx) = hv;
                    *(ushort2*)(olz + idx) = lv;
                }
            }
        }
    }
}

// ---------------- RoPE ----------------
__device__ __forceinline__ float rope_pval(int l, int m)
{
    int i = (m < 32) ? m : m - 32;
    float inv = powf(10000.f, -(float)(2 * i) / 64.f);
    float ang = (float)l * inv;
    return (m < 32) ? cosf(ang) : sinf(ang);
}

__global__ __launch_bounds__(256) void rope_kernel(const float* __restrict__ in, float* __restrict__ out)
{
    int idx = blockIdx.x * blockDim.x + threadIdx.x;
    if (idx >= Bb * Ls * Hh * 32) return;
    int j = idx & 31;
    int h = (idx >> 5) & (Hh - 1);
    int bl = idx >> 9;
    int l = bl & (Ls - 1);
    long base = (long)bl * Ds + h * HDd;
    float xe = in[base + 2 * j];
    float xo = in[base + 2 * j + 1];
    float c = rope_pval(l, 2 * j);
    float s = rope_pval(l, 2 * j + 1);
    out[base + j] = xe * c - xo * s;
    out[base + 32 + j] = xe * s + xo * c;
}

// ---------------- fused attention (R3 proven, fexp + split-emitting output) ----------------
#define ATTN_SMEM_FLOATS (64*64 + 3*64*68 + 64)

__global__ __launch_bounds__(256) void attn_kernel(
    const float* __restrict__ Q, const float* __restrict__ Kp,
    const float* __restrict__ Vp, unsigned short* __restrict__ Oh,
    unsigned short* __restrict__ Ol)
{
    extern __shared__ float sm[];
    float* sq = sm;
    float* sk = sq + 64 * 64;
    float* sv = sk + 64 * 68;
    float* ss = sv + 64 * 68;
    float* salpha = ss + 64 * 68;

    int tid = threadIdx.x;
    int bh = blockIdx.y;
    int b = bh >> 4;
    int h = bh & 15;
    int q0 = blockIdx.x * 64;
    int hb = h * HDd;
    float slope = exp2f(-0.5f * (float)h);

    {
        int r = tid >> 4;
        int d0 = (tid & 15) * 4;
#pragma unroll
        for (int cc = 0; cc < 4; cc++) {
            int rr = r + cc * 16;
            float4 v = *(const float4*)&Q[((long)(b * Ls + q0 + rr)) * Ds + hb + d0];
            *(float4*)&sq[rr * 64 + d0] = v;
        }
    }

    int ty = tid >> 4, tx = tid & 15;
    int r0 = ty * 4, c0 = tx * 4;
    int srow = tid >> 2, spart = tid & 3;

    float acc_o[4][4];
#pragma unroll
    for (int i = 0; i < 4; i++)
#pragma unroll
        for (int j = 0; j < 4; j++) acc_o[i][j] = 0.f;

    float mrow = -1e30f, lrow = 0.f;

    for (int k0 = 0; k0 < Ls; k0 += 64) {
        __syncthreads();
        {
            int c = tid >> 4;
            int d0 = (tid & 15) * 4;
#pragma unroll
            for (int cc = 0; cc < 4; cc++) {
                int rr = c + cc * 16;
                long gidx = ((long)(b * Ls + k0 + rr)) * Ds + hb + d0;
                *(float4*)&sk[rr * 68 + d0] = *(const float4*)&Kp[gidx];
                *(float4*)&sv[rr * 68 + d0] = *(const float4*)&Vp[gidx];
            }
        }
        __syncthreads();

        float acc[4][4];
#pragma unroll
        for (int i = 0; i < 4; i++)
#pragma unroll
            for (int j = 0; j < 4; j++) acc[i][j] = 0.f;

#pragma unroll 4
        for (int d0 = 0; d0 < 64; d0 += 4) {
            float4 a4[4], b4[4];
#pragma unroll
            for (int i = 0; i < 4; i++) a4[i] = *(const float4*)&sq[(r0 + i) * 64 + d0];
#pragma unroll
            for (int j = 0; j < 4; j++) b4[j] = *(const float4*)&sk[(c0 + j) * 68 + d0];
#pragma unroll
            for (int i = 0; i < 4; i++) {
                float ax = a4[i].x, ay = a4[i].y, az = a4[i].z, aw = a4[i].w;
#pragma unroll
                for (int j = 0; j < 4; j++) {
                    acc[i][j] = fmaf(ax, b4[j].x, acc[i][j]);
                    acc[i][j] = fmaf(ay, b4[j].y, acc[i][j]);
                    acc[i][j] = fmaf(az, b4[j].z, acc[i][j]);
                    acc[i][j] = fmaf(aw, b4[j].w, acc[i][j]);
                }
            }
        }
#pragma unroll
        for (int i = 0; i < 4; i++) {
            int qi = q0 + r0 + i;
            float vv0 = acc[i][0] * 0.125f + slope * fmaxf((float)(qi - (k0 + c0 + 0)), 0.f);
            float vv1 = acc[i][1] * 0.125f + slope * fmaxf((float)(qi - (k0 + c0 + 1)), 0.f);
            float vv2 = acc[i][2] * 0.125f + slope * fmaxf((float)(qi - (k0 + c0 + 2)), 0.f);
            float vv3 = acc[i][3] * 0.125f + slope * fmaxf((float)(qi - (k0 + c0 + 3)), 0.f);
            float4 w;
            w.x = vv0; w.y = vv1; w.z = vv2; w.w = vv3;
            *(float4*)&ss[(r0 + i) * 68 + c0] = w;
        }
        __syncthreads();

        {
            int cbase = spart * 16;
            float tmax = -1e30f;
#pragma unroll
            for (int c = 0; c < 16; c++) tmax = fmaxf(tmax, ss[srow * 68 + cbase + c]);
            tmax = fmaxf(tmax, __shfl_xor_sync(0xffffffffu, tmax, 1));
            tmax = fmaxf(tmax, __shfl_xor_sync(0xffffffffu, tmax, 2));
            float mnew = fmaxf(mrow, tmax);
            float alpha = fexp(mrow - mnew);
            float psum = 0.f;
#pragma unroll
            for (int c = 0; c < 16; c++) {
                float p = fexp(ss[srow * 68 + cbase + c] - mnew);
                ss[srow * 68 + cbase + c] = p;
                psum += p;
            }
            psum += __shfl_xor_sync(0xffffffffu, psum, 1);
            psum += __shfl_xor_sync(0xffffffffu, psum, 2);
            lrow = lrow * alpha + psum;
            mrow = mnew;
            if (spart == 0) salpha[srow] = alpha;
        }
        __syncthreads();

        {
            float al0 = salpha[r0 + 0];
            float al1 = salpha[r0 + 1];
            float al2 = salpha[r0 + 2];
            float al3 = salpha[r0 + 3];
#pragma unroll
            for (int j = 0; j < 4; j++) {
                acc_o[0][j] *= al0;
                acc_o[1][j] *= al1;
                acc_o[2][j] *= al2;
                acc_o[3][j] *= al3;
            }
#pragma unroll 4
            for (int cc0 = 0; cc0 < 64; cc0 += 4) {
                float4 p4[4], v4[4];
#pragma unroll
                for (int i = 0; i < 4; i++) p4[i] = *(const float4*)&ss[(r0 + i) * 68 + cc0];
#pragma unroll
                for (int c = 0; c < 4; c++) v4[c] = *(const float4*)&sv[(cc0 + c) * 68 + c0];
#pragma unroll
                for (int i = 0; i < 4; i++) {
                    float px = p4[i].x, py = p4[i].y, pz = p4[i].z, pw = p4[i].w;
                    acc_o[i][0] = fmaf(px, v4[0].x, acc_o[i][0]);
                    acc_o[i][1] = fmaf(px, v4[0].y, acc_o[i][1]);
                    acc_o[i][2] = fmaf(px, v4[0].z, acc_o[i][2]);
                    acc_o[i][3] = fmaf(px, v4[0].w, acc_o[i][3]);
                    acc_o[i][0] = fmaf(py, v4[1].x, acc_o[i][0]);
                    acc_o[i][1] = fmaf(py, v4[1].y, acc_o[i][1]);
                    acc_o[i][2] = fmaf(py, v4[1].z, acc_o[i][2]);
                    acc_o[i][3] = fmaf(py, v4[1].w, acc_o[i][3]);
                    acc_o[i][0] = fmaf(pz, v4[2].x, acc_o[i][0]);
                    acc_o[i][1] = fmaf(pz, v4[2].y, acc_o[i][1]);
                    acc_o[i][2] = fmaf(pz, v4[2].z, acc_o[i][2]);
                    acc_o[i][3] = fmaf(pz, v4[2].w, acc_o[i][3]);
                    acc_o[i][0] = fmaf(pw, v4[3].x, acc_o[i][0]);
                    acc_o[i][1] = fmaf(pw, v4[3].y, acc_o[i][1]);
                    acc_o[i][2] = fmaf(pw, v4[3].z, acc_o[i][2]);
                    acc_o[i][3] = fmaf(pw, v4[3].w, acc_o[i][3]);
                }
            }
        }
    }

    __syncthreads();
    if (spart == 0) salpha[srow] = 1.f / lrow;
    __syncthreads();
#pragma unroll
    for (int i = 0; i < 4; i++) {
        float inv = salpha[r0 + i];
        float w0 = acc_o[i][0] * inv;
        float w1 = acc_o[i][1] * inv;
        float w2 = acc_o[i][2] * inv;
        float w3 = acc_o[i][3] * inv;
        long base = ((long)(b * Ls + q0 + r0 + i)) * Ds + hb + c0;
        ushort4 hv, lv;
        split2(w0, hv.x, lv.x);
        split2(w1, hv.y, lv.y);
        split2(w2, hv.z, lv.z);
        split2(w3, hv.w, lv.w);
        *(ushort4*)&Oh[base] = hv;
        *(ushort4*)&Ol[base] = lv;
    }
}

// ---------------- LayerNorm (optional fp32 out, optional split out) ----------------
__global__ __launch_bounds__(256) void ln_kernel(
    const float* __restrict__ x, const float* __restrict__ g, const float* __restrict__ bb,
    const float* __restrict__ res, float* __restrict__ out,
    unsigned short* __restrict__ oh, unsigned short* __restrict__ ol)
{
    int row = blockIdx.x;
    const float* xr = x + (long)row * Ds;
    __shared__ float sx[Ds];
    __shared__ float sred[8];
    __shared__ float s_mean, s_rstd;
    int tid = threadIdx.x;

    float s = 0.f;
    for (int i = tid; i < Ds; i += 256) {
        float v = xr[i];
        sx[i] = v;
        s += v;
    }
#pragma unroll
    for (int o = 16; o > 0; o >>= 1) s += __shfl_down_sync(0xffffffffu, s, o);
    if ((tid & 31) == 0) sred[tid >> 5] = s;
    __syncthreads();
    if (tid == 0) {
        float t = 0.f;
        for (int i = 0; i < 8; i++) t += sred[i];
        s_mean = t / (float)Ds;
    }
    __syncthreads();
    float m = s_mean;
    float vs = 0.f;
    for (int i = tid; i < Ds; i += 256) {
        float d = sx[i] - m;
        vs += d * d;
    }
#pragma unroll
    for (int o = 16; o > 0; o >>= 1) vs += __shfl_down_sync(0xffffffffu, vs, o);
    if ((tid & 31) == 0) sred[tid >> 5] = vs;
    __syncthreads();
    if (tid == 0) {
        float t = 0.f;
        for (int i = 0; i < 8; i++) t += sred[i];
        s_rstd = rsqrtf(t / (float)Ds + EPSf);
    }
    __syncthreads();
    float rs = s_rstd;
    for (int i = tid; i < Ds; i += 256) {
        float v = (sx[i] - m) * rs * g[i] + bb[i];
        if (res) v += res[(long)row * Ds + i];
        long idx = (long)row * Ds + i;
        if (out) out[idx] = v;
        if (oh) {
            unsigned short h, l;
            split2(v, h, l);
            oh[idx] = h;
            ol[idx] = l;
        }
    }
}

// ---------------- GLU ----------------
__global__ __launch_bounds__(256) void glu_kernel(const float* __restrict__ hin, float* __restrict__ out)
{
    long idx = (long)blockIdx.x * blockDim.x + threadIdx.x;
    if (idx >= (long)BLn * Ds) return;
    long row = idx / Ds;
    int d = (int)(idx % Ds);
    float a = hin[row * 2 * Ds + d];
    float bgate = hin[row * 2 * Ds + Ds + d];
    out[idx] = a * (1.f / (1.f + expf(-bgate)));
}

// ---------------- depthwise conv + bn affine + hardswish -> split out ----------------
__global__ __launch_bounds__(256) void dwconv_kernel(
    const float* __restrict__ in, const float* __restrict__ w, const float* __restrict__ wb,
    const float* __restrict__ bng, const float* __restrict__ bnb,
    unsigned short* __restrict__ oh, unsigned short* __restrict__ ol)
{
    long idx = (long)blockIdx.x * blockDim.x + threadIdx.x;
    if (idx >= (long)BLn * Ds) return;
    long row = idx / Ds;
    int d = (int)(idx % Ds);
    int b = (int)(row / Ls);
    int l = (int)(row % Ls);
    float acc = 0.f;
#pragma unroll
    for (int m = 0; m < 5; m++) {
        int lsl = l + 2 - m;
        if (lsl >= 0 && lsl < Ls)
            acc = fmaf(w[d * 5 + m], in[((long)b * Ls + lsl) * Ds + d], acc);
    }
    float bnscale = rsqrtf(1.f + EPSf);
    float y = (acc + wb[d]) * bnscale * bng[d] + bnb[d];
    float r6 = fminf(fmaxf(y + 3.f, 0.f), 6.f);
    float v = y * r6 * (1.f / 6.f);
    unsigned short h, l2;
    split2(v, h, l2);
    oh[idx] = h;
    ol[idx] = l2;
}

// ---------------- add broadcast row 0 (per batch) ----------------
__global__ __launch_bounds__(256) void addrow0_kernel(float* __restrict__ io, const float* __restrict__ src)
{
    long idx = (long)blockIdx.x * blockDim.x + threadIdx.x;
    if (idx >= (long)BLn * Ds) return;
    long row = idx / Ds;
    int d = (int)(idx % Ds);
    int b = (int)(row / Ls);
    io[idx] += src[(long)b * Ls * Ds + d];
}

// ---------------- host helpers ----------------
static void run_split(const float* x, unsigned short* hi, unsigned short* lo, long n)
{
    long n4 = n / 4;
    split_kernel<<<(int)((n4 + 255) / 256), 256>>>(x, hi, lo, n4 * 4);
}

static void run_splitT(const float* x, unsigned short* hiT, unsigned short* loT,
                       int R, int C, int batch)
{
    dim3 grid(C / 32, R / 32, batch);
    dim3 blk(32, 8);
    splitT_kernel<<<grid, blk>>>(x, hiT, loT, R, C, (long)R * C);
}

static void run_bgemm(const unsigned short* Ah, const unsigned short* Al,
                      const unsigned short* Bh, const unsigned short* Bl,
                      const float* bias, const float* addp, float* C,
                      unsigned short* oh, unsigned short* ol,
                      int M, int N, int K, int batch, long sB, long sC,
                      int bias_mode, int act)
{
    dim3 grid(N / 128, M / 128, batch);
    bgemm_kernel<<<grid, 256, BG_SMEM_BYTES>>>(Ah, Al, Bh, Bl, bias, addp, C,
                                               oh, ol, M, N, K, sB, sC, bias_mode, act);
}

extern "C" void kernel_launch(void* const* d_in, const int* in_sizes, int n_in,
                              void* d_out, int out_size)
{
    const float* p_memory = (const float*)d_in[0];
    const float* p_wq = (const float*)d_in[1];
    const float* p_bq = (const float*)d_in[2];
    const float* p_wk = (const float*)d_in[3];
    const float* p_bk = (const float*)d_in[4];
    const float* p_wv = (const float*)d_in[5];
    const float* p_bv = (const float*)d_in[6];
    const float* p_wo = (const float*)d_in[7];
    const float* p_bo = (const float*)d_in[8];
    const float* p_n1g = (const float*)d_in[9];
    const float* p_n1b = (const float*)d_in[10];
    const float* p_clng = (const float*)d_in[11];
    const float* p_clnb = (const float*)d_in[12];
    const float* p_pw1w = (const float*)d_in[13];
    const float* p_pw1b = (const float*)d_in[14];
    const float* p_dww = (const float*)d_in[15];
    const float* p_dwb = (const float*)d_in[16];
    const float* p_bng = (const float*)d_in[17];
    const float* p_bnb = (const float*)d_in[18];
    const float* p_pw2w = (const float*)d_in[19];
    const float* p_pw2b = (const float*)d_in[20];
    const float* p_projw = (const float*)d_in[21];
    const float* p_projb = (const float*)d_in[22];
    const float* p_proj2w = (const float*)d_in[23];
    const float* p_proj2b = (const float*)d_in[24];
    const float* p_lin1w = (const float*)d_in[25];
    const float* p_lin1b = (const float*)d_in[26];
    const float* p_lin2w = (const float*)d_in[27];
    const float* p_lin2b = (const float*)d_in[28];
    const float* p_n3g = (const float*)d_in[29];
    const float* p_n3b = (const float*)d_in[30];
    float* p_out = (float*)d_out;

    float* s_stage = 0;
    float* s_q = 0;
    float* s_k = 0;
    float* s_v = 0;
    float* s_tgt2 = 0;
    float* s_mem = 0;
    float* s_h2 = 0;
    float* s_glu = 0;
    float* s_conv = 0;
    float* s_mem2 = 0;
    float* s_sum = 0;
    unsigned short* s_ah = 0;
    unsigned short* s_al = 0;
    unsigned short* s_bh = 0;
    unsigned short* s_bl = 0;
    unsigned short* s_ch = 0;
    unsigned short* s_cl = 0;
    cudaGetSymbolAddress((void**)&s_stage, g_stage);
    cudaGetSymbolAddress((void**)&s_q, g_q);
    cudaGetSymbolAddress((void**)&s_k, g_k);
    cudaGetSymbolAddress((void**)&s_v, g_v);
    cudaGetSymbolAddress((void**)&s_tgt2, g_tgt2);
    cudaGetSymbolAddress((void**)&s_mem, g_mem);
    cudaGetSymbolAddress((void**)&s_h2, g_h2);
    cudaGetSymbolAddress((void**)&s_glu, g_glu);
    cudaGetSymbolAddress((void**)&s_conv, g_conv);
    cudaGetSymbolAddress((void**)&s_mem2, g_mem2);
    cudaGetSymbolAddress((void**)&s_sum, g_sum);
    cudaGetSymbolAddress((void**)&s_ah, g_ah);
    cudaGetSymbolAddress((void**)&s_al, g_al);
    cudaGetSymbolAddress((void**)&s_bh, g_bh);
    cudaGetSymbolAddress((void**)&s_bl, g_bl);
    cudaGetSymbolAddress((void**)&s_ch, g_ch);
    cudaGetSymbolAddress((void**)&s_cl, g_cl);

    cudaFuncSetAttribute(attn_kernel, cudaFuncAttributeMaxDynamicSharedMemorySize,
                         ATTN_SMEM_FLOATS * (int)sizeof(float));
    cudaFuncSetAttribute(bgemm_kernel, cudaFuncAttributeMaxDynamicSharedMemorySize,
                         BG_SMEM_BYTES);

    const long eBLD = (long)BLn * Ds;
    int ew_grid = (int)((eBLD + 255) / 256);
    int rope_grid = (Bb * Ls * Hh * 32) / 256;

    // q/k/v projections + RoPE
    run_split(p_memory, s_ah, s_al, eBLD);
    run_split(p_wq, s_bh, s_bl, (long)Ds * Ds);
    run_bgemm(s_ah, s_al, s_bh, s_bl, p_bq, 0, s_stage, 0, 0, BLn, Ds, Ds, 1, 0, 0, 1, 0);
    rope_kernel<<<rope_grid, 256>>>(s_stage, s_q);
    run_split(p_wk, s_bh, s_bl, (long)Ds * Ds);
    run_bgemm(s_ah, s_al, s_bh, s_bl, p_bk, 0, s_stage, 0, 0, BLn, Ds, Ds, 1, 0, 0, 1, 0);
    rope_kernel<<<rope_grid, 256>>>(s_stage, s_k);
    run_split(p_wv, s_bh, s_bl, (long)Ds * Ds);
    run_bgemm(s_ah, s_al, s_bh, s_bl, p_bv, 0, s_v, 0, 0, BLn, Ds, Ds, 1, 0, 0, 1, 0);

    // fused attention (emits bf16 hi/lo of O directly)
    {
        dim3 agrid(Ls / 64, Bb * Hh);
        attn_kernel<<<agrid, 256, ATTN_SMEM_FLOATS * sizeof(float)>>>(s_q, s_k, s_v, s_ah, s_al);
    }

    // output projection, residual + LN
    run_split(p_wo, s_bh, s_bl, (long)Ds * Ds);
    run_bgemm(s_ah, s_al, s_bh, s_bl, p_bo, 0, s_tgt2, 0, 0, BLn, Ds, Ds, 1, 0, 0, 1, 0);
    ln_kernel<<<BLn, 256>>>(s_tgt2, p_n1g, p_n1b, p_memory, s_mem, 0, 0);

    // conv block: cln LN emits split directly (pw1 A)
    ln_kernel<<<BLn, 256>>>(s_mem, p_clng, p_clnb, 0, 0, s_ah, s_al);
    run_split(p_pw1w, s_bh, s_bl, (long)Ds * 2 * Ds);
    run_bgemm(s_ah, s_al, s_bh, s_bl, p_pw1b, 0, s_h2, 0, 0, BLn, 2 * Ds, Ds, 1, 0, 0, 1, 0);
    glu_kernel<<<ew_grid, 256>>>(s_h2, s_glu);
    dwconv_kernel<<<ew_grid, 256>>>(s_glu, p_dww, p_dwb, p_bng, p_bnb, s_ah, s_al);
    run_split(p_pw2w, s_bh, s_bl, (long)Ds * Ds);
    run_bgemm(s_ah, s_al, s_bh, s_bl, p_pw2b, 0, s_conv, 0, 0, BLn, Ds, Ds, 1, 0, 0, 1, 0);
    addrow0_kernel<<<ew_grid, 256>>>(s_conv, s_mem);

    // proj branch: proj = projw^T @ mem (per batch); emits split only
    run_splitT(p_projw, s_ah, s_al, Ls, Ls, 1);
    run_split(s_mem, s_bh, s_bl, eBLD);
    run_bgemm(s_ah, s_al, s_bh, s_bl, p_projb, 0, 0, s_ch, s_cl, Ls, Ds, Ls, Bb,
              (long)Ls * Ds, (long)Ls * Ds, 2, 0);
    run_split(p_proj2w, s_bh, s_bl, (long)Ds * Ds);
    run_bgemm(s_ch, s_cl, s_bh, s_bl, p_proj2b, s_conv, s_mem2, s_ah, s_al,
              BLn, Ds, Ds, 1, 0, 0, 1, 0);  // mem2 = proj2 + conv (fp32 + split)

    // FFN: lin1 + fused gelu emits split only; lin2 adds mem2
    run_split(p_lin1w, s_bh, s_bl, (long)Ds * FFs);
    run_bgemm(s_ah, s_al, s_bh, s_bl, p_lin1b, 0, 0, s_ch, s_cl,
              BLn, FFs, Ds, 1, 0, 0, 1, 1);
    run_split(p_lin2w, s_bh, s_bl, (long)FFs * Ds);
    run_bgemm(s_ch, s_cl, s_bh, s_bl, p_lin2b, s_mem2, s_sum, 0, 0,
              BLn, Ds, FFs, 1, 0, 0, 1, 0);

    // final LN -> output
    ln_kernel<<<BLn, 256>>>(s_sum, p_n3g, p_n3b, 0, p_out, 0, 0);
}

// round 7
// speedup vs baseline: 1.4946x; 1.4946x over previous
#include <cuda_runtime.h>
#include <cuda_bf16.h>
#include <math.h>

#define Bb 2
#define Ls 2048
#define Ds 1024
#define Hh 16
#define HDd 64
#define FFs 4096
#define BLn (Bb*Ls)
#define EPSf 1e-5f

// ---------------- scratch (static device memory) ----------------
__device__ float g_stage[BLn*Ds];
__device__ float g_v[BLn*Ds];
__device__ float g_tgt2[BLn*Ds];
__device__ float g_mem[BLn*Ds];
__device__ float g_h2[BLn*2*Ds];
__device__ float g_glu[BLn*Ds];
__device__ float g_conv[BLn*Ds];
__device__ float g_mem2[BLn*Ds];
__device__ float g_sum[BLn*Ds];
__device__ unsigned short g_ah[16777216];
__device__ unsigned short g_al[16777216];
__device__ unsigned short g_bh[4194304];
__device__ unsigned short g_bl[4194304];
__device__ unsigned short g_ch[16777216];
__device__ unsigned short g_cl[16777216];
// attention operands, layout [bh][l][d]
__device__ unsigned short g_qh2[4194304];
__device__ unsigned short g_ql2[4194304];
__device__ unsigned short g_kh2[4194304];
__device__ unsigned short g_kl2[4194304];
__device__ unsigned short g_vh2[4194304];
__device__ unsigned short g_vl2[4194304];

// ---------------- helpers ----------------
__device__ __forceinline__ float fexp(float x)
{
    float t = x * 1.442695041f;
    t = fmaxf(t, -126.f);
    float fn = t + 12582912.f;
    int n = __float_as_int(fn) - 0x4B400000;
    float f = t - (fn - 12582912.f);
    float p = 1.33335581e-3f;
    p = fmaf(p, f, 9.61812910e-3f);
    p = fmaf(p, f, 5.55041087e-2f);
    p = fmaf(p, f, 2.40226507e-1f);
    p = fmaf(p, f, 6.93147180e-1f);
    p = fmaf(p, f, 1.0f);
    return __int_as_float((n + 127) << 23) * p;
}

__device__ __forceinline__ float gelu_exact(float v)
{
    return 0.5f * v * (1.f + erff(v * 0.70710678118654752f));
}

__device__ __forceinline__ void split2(float v, unsigned short& h, unsigned short& l)
{
    __nv_bfloat16 hb = __float2bfloat16_rn(v);
    h = __bfloat16_as_ushort(hb);
    l = __bfloat16_as_ushort(__float2bfloat16_rn(v - __bfloat162float(hb)));
}

// ---------------- split fp32 -> bf16 hi/lo ----------------
__global__ __launch_bounds__(256) void split_kernel(
    const float* __restrict__ x, unsigned short* __restrict__ hi,
    unsigned short* __restrict__ lo, long n)
{
    long i = ((long)blockIdx.x * 256 + threadIdx.x) * 4;
    if (i >= n) return;
    float4 v = *(const float4*)(x + i);
    ushort4 hv, lv;
    split2(v.x, hv.x, lv.x);
    split2(v.y, hv.y, lv.y);
    split2(v.z, hv.z, lv.z);
    split2(v.w, hv.w, lv.w);
    *(ushort4*)(hi + i) = hv;
    *(ushort4*)(lo + i) = lv;
}

// ---------------- transpose + split ----------------
__global__ __launch_bounds__(256) void splitT_kernel(
    const float* __restrict__ in, unsigned short* __restrict__ hiT,
    unsigned short* __restrict__ loT, int R, int C, long sz)
{
    __shared__ float t[32][33];
    const float* inz = in + (long)blockIdx.z * sz;
    unsigned short* hz = hiT + (long)blockIdx.z * sz;
    unsigned short* lz = loT + (long)blockIdx.z * sz;
    int tx = threadIdx.x, ty = threadIdx.y;
    int x = blockIdx.x * 32 + tx;
    int y0 = blockIdx.y * 32;
#pragma unroll
    for (int j = 0; j < 32; j += 8)
        t[ty + j][tx] = inz[(long)(y0 + ty + j) * C + x];
    __syncthreads();
    int ox = blockIdx.y * 32 + tx;
    int oy0 = blockIdx.x * 32;
#pragma unroll
    for (int j = 0; j < 32; j += 8) {
        float val = t[tx][ty + j];
        unsigned short h, l;
        split2(val, h, l);
        hz[(long)(oy0 + ty + j) * R + ox] = h;
        lz[(long)(oy0 + ty + j) * R + ox] = l;
    }
}

// ---------------- mma helpers ----------------
__device__ __forceinline__ unsigned smem_u32(const void* p)
{
    return (unsigned)__cvta_generic_to_shared(p);
}
__device__ __forceinline__ void cp16(unsigned s, const void* g)
{
    asm volatile("cp.async.cg.shared.global [%0], [%1], 16;" :: "r"(s), "l"(g));
}
__device__ __forceinline__ void cp_commit()
{
    asm volatile("cp.async.commit_group;");
}
__device__ __forceinline__ void cp_wait1()
{
    asm volatile("cp.async.wait_group 1;");
}
__device__ __forceinline__ void cp_wait0()
{
    asm volatile("cp.async.wait_group 0;");
}
__device__ __forceinline__ void ldsm4(unsigned& r0, unsigned& r1, unsigned& r2, unsigned& r3, unsigned a)
{
    asm volatile("ldmatrix.sync.aligned.m8n8.x4.shared.b16 {%0,%1,%2,%3}, [%4];"
        : "=r"(r0), "=r"(r1), "=r"(r2), "=r"(r3) : "r"(a));
}
__device__ __forceinline__ void ldsm2(unsigned& r0, unsigned& r1, unsigned a)
{
    asm volatile("ldmatrix.sync.aligned.m8n8.x2.shared.b16 {%0,%1}, [%2];"
        : "=r"(r0), "=r"(r1) : "r"(a));
}
__device__ __forceinline__ void ldsm2t(unsigned& r0, unsigned& r1, unsigned a)
{
    asm volatile("ldmatrix.sync.aligned.m8n8.x2.trans.shared.b16 {%0,%1}, [%2];"
        : "=r"(r0), "=r"(r1) : "r"(a));
}
__device__ __forceinline__ void mma16816(float* d, const unsigned* a, const unsigned* b)
{
    asm volatile("mma.sync.aligned.m16n8k16.row.col.f32.bf16.bf16.f32 "
        "{%0,%1,%2,%3}, {%4,%5,%6,%7}, {%8,%9}, {%0,%1,%2,%3};"
        : "+f"(d[0]), "+f"(d[1]), "+f"(d[2]), "+f"(d[3])
        : "r"(a[0]), "r"(a[1]), "r"(a[2]), "r"(a[3]), "r"(b[0]), "r"(b[1]));
}

// ---------------- bf16-split tensor-core GEMM (proven) ----------------
#define LDA_P 40
#define LDB_P 136
#define OFF_AL (128*40)
#define OFF_BH (2*128*40)
#define OFF_BL (2*128*40 + 32*136)
#define STAGE_ELEMS (2*128*40 + 2*32*136)
#define BG_SMEM_BYTES (2*STAGE_ELEMS*2)

__global__ __launch_bounds__(256, 1) void bgemm_kernel(
    const unsigned short* __restrict__ Ah, const unsigned short* __restrict__ Al,
    const unsigned short* __restrict__ Bh, const unsigned short* __restrict__ Bl,
    const float* __restrict__ bias, const float* __restrict__ addp,
    float* __restrict__ C, unsigned short* __restrict__ oh,
    unsigned short* __restrict__ ol, int M, int N, int K,
    long sB, long sC, int bias_mode, int act)
{
    extern __shared__ unsigned short smem[];
    const int tid = threadIdx.x;
    const int lane = tid & 31;
    const int warp = tid >> 5;
    const int bm = blockIdx.y * 128;
    const int bn = blockIdx.x * 128;
    const unsigned short* Bhz = Bh + (long)blockIdx.z * sB;
    const unsigned short* Blz = Bl + (long)blockIdx.z * sB;
    float* Cz = C ? (C + (long)blockIdx.z * sC) : (float*)0;
    unsigned short* ohz = oh ? (oh + (long)blockIdx.z * sC) : (unsigned short*)0;
    unsigned short* olz = ol ? (ol + (long)blockIdx.z * sC) : (unsigned short*)0;
    const float* addz = addp ? (addp + (long)blockIdx.z * sC) : (const float*)0;
    const int m0 = (warp & 1) * 64;
    const int n0 = (warp >> 1) * 32;

    const int ar0 = tid >> 1;
    const int ac0 = (tid & 1) * 16;
    const int br0 = tid >> 4;
    const int bc0 = (tid & 15) * 8;

    float acc[4][4][4];
#pragma unroll
    for (int mi = 0; mi < 4; mi++)
#pragma unroll
        for (int ni = 0; ni < 4; ni++)
#pragma unroll
            for (int qq = 0; qq < 4; qq++) acc[mi][ni][qq] = 0.f;

    const int nIter = K >> 5;

#pragma unroll 1
    for (int it = 0; it < nIter + 1; ++it) {
        if (it < nIter) {
            unsigned short* st = smem + (it & 1) * STAGE_ELEMS;
            int k0 = it << 5;
            {
                long ga = (long)(bm + ar0) * K + k0 + ac0;
                cp16(smem_u32(st + ar0 * LDA_P + ac0), Ah + ga);
                cp16(smem_u32(st + ar0 * LDA_P + ac0 + 8), Ah + ga + 8);
                cp16(smem_u32(st + OFF_AL + ar0 * LDA_P + ac0), Al + ga);
                cp16(smem_u32(st + OFF_AL + ar0 * LDA_P + ac0 + 8), Al + ga + 8);
            }
            {
                long gb0 = (long)(k0 + br0) * N + bn + bc0;
                long gb1 = (long)(k0 + br0 + 16) * N + bn + bc0;
                cp16(smem_u32(st + OFF_BH + br0 * LDB_P + bc0), Bhz + gb0);
                cp16(smem_u32(st + OFF_BH + (br0 + 16) * LDB_P + bc0), Bhz + gb1);
                cp16(smem_u32(st + OFF_BL + br0 * LDB_P + bc0), Blz + gb0);
                cp16(smem_u32(st + OFF_BL + (br0 + 16) * LDB_P + bc0), Blz + gb1);
            }
            cp_commit();
        }
        if (it == 0) continue;
        if (it < nIter) cp_wait1(); else cp_wait0();
        __syncthreads();

        unsigned short* cur = smem + ((it - 1) & 1) * STAGE_ELEMS;
#pragma unroll
        for (int ks = 0; ks < 32; ks += 16) {
            unsigned afh[4][4], afl[4][4], bfh[4][2], bfl[4][2];
#pragma unroll
            for (int mi = 0; mi < 4; mi++) {
                int row = m0 + mi * 16 + (lane & 15);
                int col = ks + (lane >> 4) * 8;
                ldsm4(afh[mi][0], afh[mi][1], afh[mi][2], afh[mi][3],
                      smem_u32(cur + row * LDA_P + col));
                ldsm4(afl[mi][0], afl[mi][1], afl[mi][2], afl[mi][3],
                      smem_u32(cur + OFF_AL + row * LDA_P + col));
            }
#pragma unroll
            for (int ni = 0; ni < 4; ni++) {
                int row = ks + (lane & 15);
                int col = n0 + ni * 8;
                ldsm2t(bfh[ni][0], bfh[ni][1], smem_u32(cur + OFF_BH + row * LDB_P + col));
                ldsm2t(bfl[ni][0], bfl[ni][1], smem_u32(cur + OFF_BL + row * LDB_P + col));
            }
#pragma unroll
            for (int mi = 0; mi < 4; mi++) {
#pragma unroll
                for (int ni = 0; ni < 4; ni++) {
                    mma16816(acc[mi][ni], afh[mi], bfh[ni]);
                    mma16816(acc[mi][ni], afh[mi], bfl[ni]);
                    mma16816(acc[mi][ni], afl[mi], bfh[ni]);
                }
            }
        }
        __syncthreads();
    }

    const int r4 = lane >> 2;
    const int c2 = (lane & 3) * 2;
#pragma unroll
    for (int mi = 0; mi < 4; mi++) {
#pragma unroll
        for (int ni = 0; ni < 4; ni++) {
            int col = bn + n0 + ni * 8 + c2;
#pragma unroll
            for (int hf = 0; hf < 2; hf++) {
                int row = bm + m0 + mi * 16 + r4 + hf * 8;
                float v0 = acc[mi][ni][hf * 2 + 0];
                float v1 = acc[mi][ni][hf * 2 + 1];
                if (bias_mode == 1) { v0 += bias[col]; v1 += bias[col + 1]; }
                if (bias_mode == 2) { float bv = bias[row]; v0 += bv; v1 += bv; }
                if (addz) {
                    v0 += addz[(long)row * N + col];
                    v1 += addz[(long)row * N + col + 1];
                }
                if (act == 1) { v0 = gelu_exact(v0); v1 = gelu_exact(v1); }
                long idx = (long)row * N + col;
                if (Cz) {
                    float2 ov;
                    ov.x = v0; ov.y = v1;
                    *(float2*)(Cz + idx) = ov;
                }
                if (ohz) {
                    ushort2 hv, lv;
                    split2(v0, hv.x, lv.x);
                    split2(v1, hv.y, lv.y);
                    *(ushort2*)(ohz + idx) = hv;
                    *(ushort2*)(olz + idx) = lv;
                }
            }
        }
    }
}

// ---------------- RoPE + split to [bh][l][d] ----------------
__device__ __forceinline__ float rope_pval(int l, int m)
{
    int i = (m < 32) ? m : m - 32;
    float inv = powf(10000.f, -(float)(2 * i) / 64.f);
    float ang = (float)l * inv;
    return (m < 32) ? cosf(ang) : sinf(ang);
}

__global__ __launch_bounds__(256) void rope_split_q(
    const float* __restrict__ in, unsigned short* __restrict__ qh,
    unsigned short* __restrict__ ql)
{
    int idx = blockIdx.x * 256 + threadIdx.x;
    if (idx >= Bb * Ls * Hh * 32) return;
    int j = idx & 31;
    int h = (idx >> 5) & 15;
    int bl = idx >> 9;
    int l = bl & (Ls - 1);
    int b = bl >> 11;
    long ibase = (long)bl * Ds + h * HDd;
    float xe = in[ibase + 2 * j];
    float xo = in[ibase + 2 * j + 1];
    float c = rope_pval(l, 2 * j);
    float s = rope_pval(l, 2 * j + 1);
    float y0 = xe * c - xo * s;
    float y1 = xe * s + xo * c;
    long obase = ((long)(b * Hh + h) * Ls + l) * HDd;
    unsigned short h0, l0, h1, l1;
    split2(y0, h0, l0);
    split2(y1, h1, l1);
    qh[obase + j] = h0;
    qh[obase + 32 + j] = h1;
    ql[obase + j] = l0;
    ql[obase + 32 + j] = l1;
}

// v reshape + split, [b l][h d] -> [bh][l][d]
__global__ __launch_bounds__(256) void vsplit_kernel(
    const float* __restrict__ in, unsigned short* __restrict__ vh,
    unsigned short* __restrict__ vl)
{
    long idx4 = (long)blockIdx.x * 256 + threadIdx.x;
    if (idx4 >= (long)BLn * Ds / 4) return;
    int d4 = (int)(idx4 & 15);
    int h = (int)((idx4 >> 4) & 15);
    long l = (idx4 >> 8) & (Ls - 1);
    long b = idx4 >> 19;
    float4 v = *(const float4*)(in + ((b * Ls + l) * Ds + h * HDd + d4 * 4));
    long o = ((b * Hh + h) * Ls + l) * HDd + d4 * 4;
    ushort4 hv, lv;
    split2(v.x, hv.x, lv.x);
    split2(v.y, hv.y, lv.y);
    split2(v.z, hv.z, lv.z);
    split2(v.w, hv.w, lv.w);
    *(ushort4*)(vh + o) = hv;
    *(ushort4*)(vl + o) = lv;
}

// ---------------- tensor-core flash attention v2 ----------------
// CTA: 128 q-rows, 8 warps x 16 rows each (warp-local softmax).
// K chunks of 64 keys; K,V staged in natural [key][d] layout.
// smem (ushort units):
#define AT2_QH 0
#define AT2_QL 9216
#define AT2_PH 18432
#define AT2_PL 27648
#define AT2_STG 36864
#define AT2_KH 0
#define AT2_KL 4608
#define AT2_VH 9216
#define AT2_VL 13824
#define AT2_STGSZ 18432
#define AT2_SMEM_BYTES ((36864 + 2*18432)*2)

__device__ __forceinline__ void at2_load_kv(
    unsigned sbase, int stage, int k0,
    const unsigned short* kh, const unsigned short* kl,
    const unsigned short* vh, const unsigned short* vl, int bh, int tid)
{
    unsigned so = (unsigned)(AT2_STG + stage * AT2_STGSZ);
#pragma unroll
    for (int i = 0; i < 2; i++) {
        int c = tid * 2 + i;          // 0..511 = 64 rows x 8 chunks
        int r = c >> 3;
        int cc = (c & 7) * 8;
        long g = ((long)bh * Ls + k0 + r) * HDd + cc;
        cp16(sbase + (so + AT2_KH + r * 72 + cc) * 2, kh + g);
        cp16(sbase + (so + AT2_KL + r * 72 + cc) * 2, kl + g);
        cp16(sbase + (so + AT2_VH + r * 72 + cc) * 2, vh + g);
        cp16(sbase + (so + AT2_VL + r * 72 + cc) * 2, vl + g);
    }
    cp_commit();
}

__global__ __launch_bounds__(256, 1) void attn2_kernel(
    const unsigned short* __restrict__ qh, const unsigned short* __restrict__ ql,
    const unsigned short* __restrict__ kh, const unsigned short* __restrict__ kl,
    const unsigned short* __restrict__ vh, const unsigned short* __restrict__ vl,
    unsigned short* __restrict__ Oh, unsigned short* __restrict__ Ol)
{
    extern __shared__ __align__(16) unsigned short sm2[];
    const int tid = threadIdx.x;
    const int lane = tid & 31;
    const int warp = tid >> 5;
    const int g = lane >> 2;
    const int tk = lane & 3;
    const int m0 = warp * 16;
    const int q0 = blockIdx.x * 128;
    const int bh = blockIdx.y;
    const int b = bh >> 4, h = bh & 15;
    const float slope = exp2f(-0.5f * (float)h);
    const unsigned sbase = smem_u32(sm2);

    // Q load (bundled into group 0 with first kv chunk)
#pragma unroll
    for (int i = 0; i < 4; i++) {
        int t = tid + i * 256;        // 0..1023 = 128 rows x 8 chunks
        int r = t >> 3;
        int cc = (t & 7) * 8;
        long gq = ((long)bh * Ls + q0 + r) * HDd + cc;
        cp16(sbase + (AT2_QH + r * 72 + cc) * 2, qh + gq);
        cp16(sbase + (AT2_QL + r * 72 + cc) * 2, ql + gq);
    }
    at2_load_kv(sbase, 0, 0, kh, kl, vh, vl, bh, tid);
    at2_load_kv(sbase, 1, 64, kh, kl, vh, vl, bh, tid);

    float acc_o[8][4];
#pragma unroll
    for (int dt = 0; dt < 8; dt++)
#pragma unroll
        for (int q = 0; q < 4; q++) acc_o[dt][q] = 0.f;
    float mstA = -1e30f, mstB = -1e30f, lstA = 0.f, lstB = 0.f;

    const int nc = Ls / 64;   // 32 chunks
#pragma unroll 1
    for (int it = 0; it < nc; ++it) {
        if (it < nc - 1) cp_wait1(); else cp_wait0();
        __syncthreads();
        unsigned so = (unsigned)(AT2_STG + (it & 1) * AT2_STGSZ);
        const int k0 = it * 64;

        // S = Q K^T (hi/lo compensated)
        float s[8][4];
#pragma unroll
        for (int nt = 0; nt < 8; nt++)
#pragma unroll
            for (int q = 0; q < 4; q++) s[nt][q] = 0.f;

#pragma unroll
        for (int ks = 0; ks < 4; ks++) {
            unsigned aqh[4], aql[4];
            int arow = m0 + (lane & 15);
            int acol = ks * 16 + (lane >> 4) * 8;
            ldsm4(aqh[0], aqh[1], aqh[2], aqh[3],
                  sbase + (AT2_QH + arow * 72 + acol) * 2);
            ldsm4(aql[0], aql[1], aql[2], aql[3],
                  sbase + (AT2_QL + arow * 72 + acol) * 2);
#pragma unroll
            for (int nt = 0; nt < 8; nt++) {
                // B from K stored [key][d]: non-trans x2
                int brow = nt * 8 + (lane & 7);
                int bcol = ks * 16 + ((lane >> 3) & 1) * 8;
                unsigned bkh[2], bkl[2];
                ldsm2(bkh[0], bkh[1], sbase + (so + AT2_KH + brow * 72 + bcol) * 2);
                ldsm2(bkl[0], bkl[1], sbase + (so + AT2_KL + brow * 72 + bcol) * 2);
                mma16816(s[nt], aqh, bkh);
                mma16816(s[nt], aqh, bkl);
                mma16816(s[nt], aql, bkh);
            }
        }

        // scale + alibi (C-fragment rows g / g+8, cols 2tk / 2tk+1)
        int qa = q0 + m0 + g;
        int qb = qa + 8;
#pragma unroll
        for (int nt = 0; nt < 8; nt++) {
            int kj = k0 + nt * 8 + 2 * tk;
            s[nt][0] = s[nt][0] * 0.125f + slope * fmaxf((float)(qa - kj), 0.f);
            s[nt][1] = s[nt][1] * 0.125f + slope * fmaxf((float)(qa - kj - 1), 0.f);
            s[nt][2] = s[nt][2] * 0.125f + slope * fmaxf((float)(qb - kj), 0.f);
            s[nt][3] = s[nt][3] * 0.125f + slope * fmaxf((float)(qb - kj - 1), 0.f);
        }

        // warp-local online softmax (rows g and g+8 of this warp's band)
        float mA = -1e30f, mB = -1e30f;
#pragma unroll
        for (int nt = 0; nt < 8; nt++) {
            mA = fmaxf(mA, fmaxf(s[nt][0], s[nt][1]));
            mB = fmaxf(mB, fmaxf(s[nt][2], s[nt][3]));
        }
        mA = fmaxf(mA, __shfl_xor_sync(0xffffffffu, mA, 1));
        mA = fmaxf(mA, __shfl_xor_sync(0xffffffffu, mA, 2));
        mB = fmaxf(mB, __shfl_xor_sync(0xffffffffu, mB, 1));
        mB = fmaxf(mB, __shfl_xor_sync(0xffffffffu, mB, 2));
        float mnA = fmaxf(mstA, mA);
        float mnB = fmaxf(mstB, mB);
        float alA = fexp(mstA - mnA);
        float alB = fexp(mstB - mnB);
        mstA = mnA;
        mstB = mnB;

        float rsA = 0.f, rsB = 0.f;
#pragma unroll
        for (int nt = 0; nt < 8; nt++) {
            float p0 = fexp(s[nt][0] - mstA);
            float p1 = fexp(s[nt][1] - mstA);
            float p2 = fexp(s[nt][2] - mstB);
            float p3 = fexp(s[nt][3] - mstB);
            s[nt][0] = p0; s[nt][1] = p1; s[nt][2] = p2; s[nt][3] = p3;
            rsA += p0 + p1;
            rsB += p2 + p3;
        }
        rsA += __shfl_xor_sync(0xffffffffu, rsA, 1);
        rsA += __shfl_xor_sync(0xffffffffu, rsA, 2);
        rsB += __shfl_xor_sync(0xffffffffu, rsB, 1);
        rsB += __shfl_xor_sync(0xffffffffu, rsB, 2);
        lstA = lstA * alA + rsA;
        lstB = lstB * alB + rsB;

#pragma unroll
        for (int dt = 0; dt < 8; dt++) {
            acc_o[dt][0] *= alA;
            acc_o[dt][1] *= alA;
            acc_o[dt][2] *= alB;
            acc_o[dt][3] *= alB;
        }

        // P -> smem (warp-private rows), hi/lo
#pragma unroll
        for (int nt = 0; nt < 8; nt++) {
            int colb = nt * 8 + 2 * tk;
            ushort2 hA, lA, hB, lB;
            split2(s[nt][0], hA.x, lA.x);
            split2(s[nt][1], hA.y, lA.y);
            split2(s[nt][2], hB.x, lB.x);
            split2(s[nt][3], hB.y, lB.y);
            *(ushort2*)(sm2 + AT2_PH + (m0 + g) * 72 + colb) = hA;
            *(ushort2*)(sm2 + AT2_PL + (m0 + g) * 72 + colb) = lA;
            *(ushort2*)(sm2 + AT2_PH + (m0 + g + 8) * 72 + colb) = hB;
            *(ushort2*)(sm2 + AT2_PL + (m0 + g + 8) * 72 + colb) = lB;
        }
        __syncwarp();

        // O += P V (hi/lo), V stored [key][d] -> trans B loads (proven pattern)
#pragma unroll
        for (int kt = 0; kt < 4; kt++) {
            unsigned aph[4], apl[4];
            int prow = m0 + (lane & 15);
            int pcol = kt * 16 + (lane >> 4) * 8;
            ldsm4(aph[0], aph[1], aph[2], aph[3],
                  sbase + (AT2_PH + prow * 72 + pcol) * 2);
            ldsm4(apl[0], apl[1], apl[2], apl[3],
                  sbase + (AT2_PL + prow * 72 + pcol) * 2);
#pragma unroll
            for (int dt = 0; dt < 8; dt++) {
                int vrow = kt * 16 + (lane & 15);
                int vcol = dt * 8;
                unsigned bvh[2], bvl[2];
                ldsm2t(bvh[0], bvh[1], sbase + (so + AT2_VH + vrow * 72 + vcol) * 2);
                ldsm2t(bvl[0], bvl[1], sbase + (so + AT2_VL + vrow * 72 + vcol) * 2);
                mma16816(acc_o[dt], aph, bvh);
                mma16816(acc_o[dt], aph, bvl);
                mma16816(acc_o[dt], apl, bvh);
            }
        }
        __syncthreads();
        if (it + 2 < nc)
            at2_load_kv(sbase, it & 1, (it + 2) * 64, kh, kl, vh, vl, bh, tid);
    }

    // normalize + emit hi/lo splits directly
    float invA = 1.f / lstA;
    float invB = 1.f / lstB;
    int rowA = q0 + m0 + g;
    int rowB = rowA + 8;
#pragma unroll
    for (int dt = 0; dt < 8; dt++) {
        int col = h * HDd + dt * 8 + 2 * tk;
        long gA = ((long)(b * Ls + rowA)) * Ds + col;
        long gB = ((long)(b * Ls + rowB)) * Ds + col;
        ushort2 hA, lA, hB, lB;
        split2(acc_o[dt][0] * invA, hA.x, lA.x);
        split2(acc_o[dt][1] * invA, hA.y, lA.y);
        split2(acc_o[dt][2] * invB, hB.x, lB.x);
        split2(acc_o[dt][3] * invB, hB.y, lB.y);
        *(ushort2*)(Oh + gA) = hA;
        *(ushort2*)(Ol + gA) = lA;
        *(ushort2*)(Oh + gB) = hB;
        *(ushort2*)(Ol + gB) = lB;
    }
}

// ---------------- LayerNorm ----------------
__global__ __launch_bounds__(256) void ln_kernel(
    const float* __restrict__ x, const float* __restrict__ g, const float* __restrict__ bb,
    const float* __restrict__ res, float* __restrict__ out,
    unsigned short* __restrict__ oh, unsigned short* __restrict__ ol)
{
    int row = blockIdx.x;
    const float* xr = x + (long)row * Ds;
    __shared__ float sx[Ds];
    __shared__ float sred[8];
    __shared__ float s_mean, s_rstd;
    int tid = threadIdx.x;

    float s = 0.f;
    for (int i = tid; i < Ds; i += 256) {
        float v = xr[i];
        sx[i] = v;
        s += v;
    }
#pragma unroll
    for (int o = 16; o > 0; o >>= 1) s += __shfl_down_sync(0xffffffffu, s, o);
    if ((tid & 31) == 0) sred[tid >> 5] = s;
    __syncthreads();
    if (tid == 0) {
        float t = 0.f;
        for (int i = 0; i < 8; i++) t += sred[i];
        s_mean = t / (float)Ds;
    }
    __syncthreads();
    float m = s_mean;
    float vs = 0.f;
    for (int i = tid; i < Ds; i += 256) {
        float d = sx[i] - m;
        vs += d * d;
    }
#pragma unroll
    for (int o = 16; o > 0; o >>= 1) vs += __shfl_down_sync(0xffffffffu, vs, o);
    if ((tid & 31) == 0) sred[tid >> 5] = vs;
    __syncthreads();
    if (tid == 0) {
        float t = 0.f;
        for (int i = 0; i < 8; i++) t += sred[i];
        s_rstd = rsqrtf(t / (float)Ds + EPSf);
    }
    __syncthreads();
    float rs = s_rstd;
    for (int i = tid; i < Ds; i += 256) {
        float v = (sx[i] - m) * rs * g[i] + bb[i];
        if (res) v += res[(long)row * Ds + i];
        long idx = (long)row * Ds + i;
        if (out) out[idx] = v;
        if (oh) {
            unsigned short hh, ll;
            split2(v, hh, ll);
            oh[idx] = hh;
            ol[idx] = ll;
        }
    }
}

// ---------------- GLU ----------------
__global__ __launch_bounds__(256) void glu_kernel(const float* __restrict__ hin, float* __restrict__ out)
{
    long idx = (long)blockIdx.x * blockDim.x + threadIdx.x;
    if (idx >= (long)BLn * Ds) return;
    long row = idx / Ds;
    int d = (int)(idx % Ds);
    float a = hin[row * 2 * Ds + d];
    float bgate = hin[row * 2 * Ds + Ds + d];
    out[idx] = a * (1.f / (1.f + expf(-bgate)));
}

// ---------------- depthwise conv + bn affine + hardswish -> split out ----------------
__global__ __launch_bounds__(256) void dwconv_kernel(
    const float* __restrict__ in, const float* __restrict__ w, const float* __restrict__ wb,
    const float* __restrict__ bng, const float* __restrict__ bnb,
    unsigned short* __restrict__ oh, unsigned short* __restrict__ ol)
{
    long idx = (long)blockIdx.x * blockDim.x + threadIdx.x;
    if (idx >= (long)BLn * Ds) return;
    long row = idx / Ds;
    int d = (int)(idx % Ds);
    int b = (int)(row / Ls);
    int l = (int)(row % Ls);
    float acc = 0.f;
#pragma unroll
    for (int m = 0; m < 5; m++) {
        int lsl = l + 2 - m;
        if (lsl >= 0 && lsl < Ls)
            acc = fmaf(w[d * 5 + m], in[((long)b * Ls + lsl) * Ds + d], acc);
    }
    float bnscale = rsqrtf(1.f + EPSf);
    float y = (acc + wb[d]) * bnscale * bng[d] + bnb[d];
    float r6 = fminf(fmaxf(y + 3.f, 0.f), 6.f);
    float v = y * r6 * (1.f / 6.f);
    unsigned short hh, ll;
    split2(v, hh, ll);
    oh[idx] = hh;
    ol[idx] = ll;
}

// ---------------- add broadcast row 0 (per batch) ----------------
__global__ __launch_bounds__(256) void addrow0_kernel(float* __restrict__ io, const float* __restrict__ src)
{
    long idx = (long)blockIdx.x * blockDim.x + threadIdx.x;
    if (idx >= (long)BLn * Ds) return;
    long row = idx / Ds;
    int d = (int)(idx % Ds);
    int b = (int)(row / Ls);
    io[idx] += src[(long)b * Ls * Ds + d];
}

// ---------------- host helpers ----------------
static void run_split(const float* x, unsigned short* hi, unsigned short* lo, long n)
{
    long n4 = n / 4;
    split_kernel<<<(int)((n4 + 255) / 256), 256>>>(x, hi, lo, n4 * 4);
}

static void run_splitT(const float* x, unsigned short* hiT, unsigned short* loT,
                       int R, int C, int batch)
{
    dim3 grid(C / 32, R / 32, batch);
    dim3 blk(32, 8);
    splitT_kernel<<<grid, blk>>>(x, hiT, loT, R, C, (long)R * C);
}

static void run_bgemm(const unsigned short* Ah, const unsigned short* Al,
                      const unsigned short* Bh, const unsigned short* Bl,
                      const float* bias, const float* addp, float* C,
                      unsigned short* oh, unsigned short* ol,
                      int M, int N, int K, int batch, long sB, long sC,
                      int bias_mode, int act)
{
    dim3 grid(N / 128, M / 128, batch);
    bgemm_kernel<<<grid, 256, BG_SMEM_BYTES>>>(Ah, Al, Bh, Bl, bias, addp, C,
                                               oh, ol, M, N, K, sB, sC, bias_mode, act);
}

extern "C" void kernel_launch(void* const* d_in, const int* in_sizes, int n_in,
                              void* d_out, int out_size)
{
    const float* p_memory = (const float*)d_in[0];
    const float* p_wq = (const float*)d_in[1];
    const float* p_bq = (const float*)d_in[2];
    const float* p_wk = (const float*)d_in[3];
    const float* p_bk = (const float*)d_in[4];
    const float* p_wv = (const float*)d_in[5];
    const float* p_bv = (const float*)d_in[6];
    const float* p_wo = (const float*)d_in[7];
    const float* p_bo = (const float*)d_in[8];
    const float* p_n1g = (const float*)d_in[9];
    const float* p_n1b = (const float*)d_in[10];
    const float* p_clng = (const float*)d_in[11];
    const float* p_clnb = (const float*)d_in[12];
    const float* p_pw1w = (const float*)d_in[13];
    const float* p_pw1b = (const float*)d_in[14];
    const float* p_dww = (const float*)d_in[15];
    const float* p_dwb = (const float*)d_in[16];
    const float* p_bng = (const float*)d_in[17];
    const float* p_bnb = (const float*)d_in[18];
    const float* p_pw2w = (const float*)d_in[19];
    const float* p_pw2b = (const float*)d_in[20];
    const float* p_projw = (const float*)d_in[21];
    const float* p_projb = (const float*)d_in[22];
    const float* p_proj2w = (const float*)d_in[23];
    const float* p_proj2b = (const float*)d_in[24];
    const float* p_lin1w = (const float*)d_in[25];
    const float* p_lin1b = (const float*)d_in[26];
    const float* p_lin2w = (const float*)d_in[27];
    const float* p_lin2b = (const float*)d_in[28];
    const float* p_n3g = (const float*)d_in[29];
    const float* p_n3b = (const float*)d_in[30];
    float* p_out = (float*)d_out;

    float* s_stage = 0;
    float* s_v = 0;
    float* s_tgt2 = 0;
    float* s_mem = 0;
    float* s_h2 = 0;
    float* s_glu = 0;
    float* s_conv = 0;
    float* s_mem2 = 0;
    float* s_sum = 0;
    unsigned short* s_ah = 0;
    unsigned short* s_al = 0;
    unsigned short* s_bh = 0;
    unsigned short* s_bl = 0;
    unsigned short* s_ch = 0;
    unsigned short* s_cl = 0;
    unsigned short* s_qh2 = 0;
    unsigned short* s_ql2 = 0;
    unsigned short* s_kh2 = 0;
    unsigned short* s_kl2 = 0;
    unsigned short* s_vh2 = 0;
    unsigned short* s_vl2 = 0;
    cudaGetSymbolAddress((void**)&s_stage, g_stage);
    cudaGetSymbolAddress((void**)&s_v, g_v);
    cudaGetSymbolAddress((void**)&s_tgt2, g_tgt2);
    cudaGetSymbolAddress((void**)&s_mem, g_mem);
    cudaGetSymbolAddress((void**)&s_h2, g_h2);
    cudaGetSymbolAddress((void**)&s_glu, g_glu);
    cudaGetSymbolAddress((void**)&s_conv, g_conv);
    cudaGetSymbolAddress((void**)&s_mem2, g_mem2);
    cudaGetSymbolAddress((void**)&s_sum, g_sum);
    cudaGetSymbolAddress((void**)&s_ah, g_ah);
    cudaGetSymbolAddress((void**)&s_al, g_al);
    cudaGetSymbolAddress((void**)&s_bh, g_bh);
    cudaGetSymbolAddress((void**)&s_bl, g_bl);
    cudaGetSymbolAddress((void**)&s_ch, g_ch);
    cudaGetSymbolAddress((void**)&s_cl, g_cl);
    cudaGetSymbolAddress((void**)&s_qh2, g_qh2);
    cudaGetSymbolAddress((void**)&s_ql2, g_ql2);
    cudaGetSymbolAddress((void**)&s_kh2, g_kh2);
    cudaGetSymbolAddress((void**)&s_kl2, g_kl2);
    cudaGetSymbolAddress((void**)&s_vh2, g_vh2);
    cudaGetSymbolAddress((void**)&s_vl2, g_vl2);

    cudaFuncSetAttribute(bgemm_kernel, cudaFuncAttributeMaxDynamicSharedMemorySize,
                         BG_SMEM_BYTES);
    cudaFuncSetAttribute(attn2_kernel, cudaFuncAttributeMaxDynamicSharedMemorySize,
                         AT2_SMEM_BYTES);

    const long eBLD = (long)BLn * Ds;
    int ew_grid = (int)((eBLD + 255) / 256);
    int rope_grid = (Bb * Ls * Hh * 32) / 256;

    // q/k/v projections + RoPE + splits (layout [bh][l][d])
    run_split(p_memory, s_ah, s_al, eBLD);
    run_split(p_wq, s_bh, s_bl, (long)Ds * Ds);
    run_bgemm(s_ah, s_al, s_bh, s_bl, p_bq, 0, s_stage, 0, 0, BLn, Ds, Ds, 1, 0, 0, 1, 0);
    rope_split_q<<<rope_grid, 256>>>(s_stage, s_qh2, s_ql2);
    run_split(p_wk, s_bh, s_bl, (long)Ds * Ds);
    run_bgemm(s_ah, s_al, s_bh, s_bl, p_bk, 0, s_stage, 0, 0, BLn, Ds, Ds, 1, 0, 0, 1, 0);
    rope_split_q<<<rope_grid, 256>>>(s_stage, s_kh2, s_kl2);
    run_split(p_wv, s_bh, s_bl, (long)Ds * Ds);
    run_bgemm(s_ah, s_al, s_bh, s_bl, p_bv, 0, s_v, 0, 0, BLn, Ds, Ds, 1, 0, 0, 1, 0);
    vsplit_kernel<<<(int)(eBLD / 4 + 255) / 256, 256>>>(s_v, s_vh2, s_vl2);

    // tensor-core flash attention (emits hi/lo splits of O)
    {
        dim3 agrid(Ls / 128, Bb * Hh);
        attn2_kernel<<<agrid, 256, AT2_SMEM_BYTES>>>(
            s_qh2, s_ql2, s_kh2, s_kl2, s_vh2, s_vl2, s_ah, s_al);
    }

    // output projection, residual + LN
    run_split(p_wo, s_bh, s_bl, (long)Ds * Ds);
    run_bgemm(s_ah, s_al, s_bh, s_bl, p_bo, 0, s_tgt2, 0, 0, BLn, Ds, Ds, 1, 0, 0, 1, 0);
    ln_kernel<<<BLn, 256>>>(s_tgt2, p_n1g, p_n1b, p_memory, s_mem, 0, 0);

    // conv block
    ln_kernel<<<BLn, 256>>>(s_mem, p_clng, p_clnb, 0, 0, s_ah, s_al);
    run_split(p_pw1w, s_bh, s_bl, (long)Ds * 2 * Ds);
    run_bgemm(s_ah, s_al, s_bh, s_bl, p_pw1b, 0, s_h2, 0, 0, BLn, 2 * Ds, Ds, 1, 0, 0, 1, 0);
    glu_kernel<<<ew_grid, 256>>>(s_h2, s_glu);
    dwconv_kernel<<<ew_grid, 256>>>(s_glu, p_dww, p_dwb, p_bng, p_bnb, s_ah, s_al);
    run_split(p_pw2w, s_bh, s_bl, (long)Ds * Ds);
    run_bgemm(s_ah, s_al, s_bh, s_bl, p_pw2b, 0, s_conv, 0, 0, BLn, Ds, Ds, 1, 0, 0, 1, 0);
    addrow0_kernel<<<ew_grid, 256>>>(s_conv, s_mem);

    // proj branch
    run_splitT(p_projw, s_ah, s_al, Ls, Ls, 1);
    run_split(s_mem, s_bh, s_bl, eBLD);
    run_bgemm(s_ah, s_al, s_bh, s_bl, p_projb, 0, 0, s_ch, s_cl, Ls, Ds, Ls, Bb,
              (long)Ls * Ds, (long)Ls * Ds, 2, 0);
    run_split(p_proj2w, s_bh, s_bl, (long)Ds * Ds);
    run_bgemm(s_ch, s_cl, s_bh, s_bl, p_proj2b, s_conv, s_mem2, s_ah, s_al,
              BLn, Ds, Ds, 1, 0, 0, 1, 0);

    // FFN
    run_split(p_lin1w, s_bh, s_bl, (long)Ds * FFs);
    run_bgemm(s_ah, s_al, s_bh, s_bl, p_lin1b, 0, 0, s_ch, s_cl,
              BLn, FFs, Ds, 1, 0, 0, 1, 1);
    run_split(p_lin2w, s_bh, s_bl, (long)FFs * Ds);
    run_bgemm(s_ch, s_cl, s_bh, s_bl, p_lin2b, s_mem2, s_sum, 0, 0,
              BLn, Ds, FFs, 1, 0, 0, 1, 0);

    // final LN -> output
    ln_kernel<<<BLn, 256>>>(s_sum, p_n3g, p_n3b, 0, p_out, 0, 0);
}